// round 5
// baseline (speedup 1.0000x reference)
#include <cuda_runtime.h>

#define HD   64
#define TT   2048
#define BB   256
#define NB   2              // batch elements per CTA
#define NCTA (BB / NB)      // 128
#define NTH  256
#define CH   64             // timestep chunk for input prefetch

typedef unsigned long long u64;

// Scratch for layer-0 hidden states (static device global — no runtime alloc)
__device__ float g_h1buf[(size_t)BB * TT * HD];

__device__ __forceinline__ u64 ffma2(u64 a, u64 b, u64 c) {
    u64 d;
    asm("fma.rn.f32x2 %0, %1, %2, %3;" : "=l"(d) : "l"(a), "l"(b), "l"(c));
    return d;
}
__device__ __forceinline__ u64 fadd2(u64 a, u64 b) {
    u64 d;
    asm("add.rn.f32x2 %0, %1, %2;" : "=l"(d) : "l"(a), "l"(b));
    return d;
}
__device__ __forceinline__ u64 pack2(float lo, float hi) {
    u64 d;
    asm("mov.b64 %0, {%1, %2};" : "=l"(d) : "f"(lo), "f"(hi));
    return d;
}
__device__ __forceinline__ float pairsum(u64 a) {
    float lo, hi;
    asm("mov.b64 {%0, %1}, %2;" : "=f"(lo), "=f"(hi) : "l"(a));
    return lo + hi;
}

// sigmoid via EX2 + MUFU.RCP (keeps IEEE div off the FMA pipe)
__device__ __forceinline__ float sigm(float x) {
    return __fdividef(1.f, 1.f + __expf(-x));
}
// tanh via exp(-2|x|) + MUFU.RCP; err ~1e-6, fine at 1e-3 tolerance
__device__ __forceinline__ float tanh_fast(float x) {
    float t = __expf(-2.f * fabsf(x));
    float r = __fdividef(1.f - t, 1.f + t);
    return copysignf(r, x);
}

// ---------------------------------------------------------------------------
// Layer 0: input dim 32. Writes h1 to g_h1buf.
// Step pipeline: phase1 = h-side FMA + activation (x-side + bias comes from
// the pipelined accumulators); phase2 = (c,h) update on 128 threads
// overlapped with ALL threads computing the NEXT step's x-side.
// ---------------------------------------------------------------------------
__global__ __launch_bounds__(NTH, 1)
void lstm_layer0(const float* __restrict__ x,
                 const float* __restrict__ Wih,   // [256,32]
                 const float* __restrict__ Whh,   // [256,64]
                 const float* __restrict__ bih,
                 const float* __restrict__ bhh)
{
    __shared__ __align__(16) float x_sh[NB][CH][32];
    __shared__ __align__(16) float h_sh[NB][HD];
    __shared__ float g_sh[NB][4 * HD];
    __shared__ float bias_sh[4 * HD];

    const int tid = threadIdx.x;
    const int g   = tid;                 // gate index 0..255
    const int b0  = blockIdx.x * NB;
    const int type = g >> 6;             // 0:i 1:f 2:g 3:o

    // This gate's weight rows, register-resident as f32x2 pairs.
    u64 wi[16], wr[32];
    {
        const u64* wip = (const u64*)(Wih + g * 32);
#pragma unroll
        for (int j = 0; j < 16; j++) wi[j] = wip[j];
        const u64* wrp = (const u64*)(Whh + g * 64);
#pragma unroll
        for (int j = 0; j < 32; j++) wr[j] = wrp[j];
    }
    bias_sh[g] = bih[g] + bhh[g];
    if (tid < NB * HD) h_sh[tid >> 6][tid & 63] = 0.f;
    float c = 0.f;                       // cell state for updater threads
    __syncthreads();
    const u64 bias2 = pack2(bias_sh[g], 0.f);   // bias folded into x-accum

    u64 xa[NB][2];                       // pipelined x-side accumulators

    for (int t0 = 0; t0 < TT; t0 += CH) {
        // Prefetch x chunk: NB*CH*32 floats (coalesced)
#pragma unroll
        for (int i = tid; i < NB * CH * 32; i += NTH) {
            int b = i / (CH * 32);
            int r = i % (CH * 32);
            x_sh[b][r >> 5][r & 31] = x[(size_t)(b0 + b) * TT * 32 + (size_t)t0 * 32 + r];
        }
        __syncthreads();

        // Chunk-head: prime x-side accumulators for step t0.
#pragma unroll
        for (int b = 0; b < NB; b++) {
            const ulonglong2* xp = (const ulonglong2*)x_sh[b][0];
            u64 x2 = bias2, x3 = 0ULL;
#pragma unroll
            for (int j = 0; j < 8; j++) {
                ulonglong2 xv = xp[j];
                x2 = ffma2(wi[2 * j],     xv.x, x2);
                x3 = ffma2(wi[2 * j + 1], xv.y, x3);
            }
            xa[b][0] = x2; xa[b][1] = x3;
        }

        for (int tt = 0; tt < CH; tt++) {
            const int t = t0 + tt;
            // --- phase 1: h-side gate accumulation + activation ---
#pragma unroll
            for (int b = 0; b < NB; b++) {
                const ulonglong2* hp = (const ulonglong2*)h_sh[b];
                u64 a0 = 0ULL, a1 = 0ULL;
#pragma unroll
                for (int j = 0; j < 16; j++) {
                    ulonglong2 hv = hp[j];
                    a0 = ffma2(wr[2 * j],     hv.x, a0);
                    a1 = ffma2(wr[2 * j + 1], hv.y, a1);
                }
                float v = pairsum(fadd2(fadd2(a0, a1), fadd2(xa[b][0], xa[b][1])));
                v = (type == 2) ? tanh_fast(v) : sigm(v);
                g_sh[b][g] = v;
            }
            __syncthreads();             // barrier A: gates published
            // --- phase 2: (c,h) update on 128 threads; all threads also
            //     precompute next step's x-side (independent of h) ---
            if (tid < NB * HD) {
                int b = tid >> 6, j = tid & 63;
                float iv = g_sh[b][j];
                float fv = g_sh[b][64 + j];
                float gv = g_sh[b][128 + j];
                float ov = g_sh[b][192 + j];
                c = fv * c + iv * gv;
                float h = ov * tanh_fast(c);
                h_sh[b][j] = h;
                g_h1buf[((size_t)(b0 + b) * TT + t) * HD + j] = h;
            }
            if (tt + 1 < CH) {
#pragma unroll
                for (int b = 0; b < NB; b++) {
                    const ulonglong2* xp = (const ulonglong2*)x_sh[b][tt + 1];
                    u64 x2 = bias2, x3 = 0ULL;
#pragma unroll
                    for (int j = 0; j < 8; j++) {
                        ulonglong2 xv = xp[j];
                        x2 = ffma2(wi[2 * j],     xv.x, x2);
                        x3 = ffma2(wi[2 * j + 1], xv.y, x3);
                    }
                    xa[b][0] = x2; xa[b][1] = x3;
                }
            }
            __syncthreads();             // barrier B: h(t) published
        }
    }
}

// ---------------------------------------------------------------------------
// Layer 1: input dim 64 (from g_h1buf). Same pipeline; output projection for
// step t runs one step late on warps 6-7 (off the updater critical path).
// ---------------------------------------------------------------------------
__global__ __launch_bounds__(NTH, 1)
void lstm_layer1(const float* __restrict__ Wih,   // [256,64]
                 const float* __restrict__ Whh,   // [256,64]
                 const float* __restrict__ bih,
                 const float* __restrict__ bhh,
                 const float* __restrict__ Wout,  // [1,64]
                 const float* __restrict__ bout,
                 float* __restrict__ out)         // [B,T,1]
{
    __shared__ __align__(16) float x_sh[NB][CH][HD];
    __shared__ __align__(16) float h_sh[NB][HD];
    __shared__ float g_sh[NB][4 * HD];
    __shared__ float bias_sh[4 * HD];
    __shared__ float wout_sh[HD];
    __shared__ float bout_sh;

    const int tid = threadIdx.x;
    const int g   = tid;
    const int b0  = blockIdx.x * NB;
    const int type = g >> 6;

    u64 wi[32], wr[32];
    {
        const u64* wip = (const u64*)(Wih + g * 64);
#pragma unroll
        for (int j = 0; j < 32; j++) wi[j] = wip[j];
        const u64* wrp = (const u64*)(Whh + g * 64);
#pragma unroll
        for (int j = 0; j < 32; j++) wr[j] = wrp[j];
    }
    bias_sh[g] = bih[g] + bhh[g];
    if (tid < HD) wout_sh[tid] = Wout[tid];
    if (tid == 0) bout_sh = bout[0];
    if (tid < NB * HD) h_sh[tid >> 6][tid & 63] = 0.f;
    float c = 0.f;
    __syncthreads();
    const u64 bias2 = pack2(bias_sh[g], 0.f);
    const float bo  = bout_sh;

    u64 xa[NB][2];

    for (int t0 = 0; t0 < TT; t0 += CH) {
        // Prefetch input chunk from layer-0 output: NB*CH*64 floats
#pragma unroll
        for (int i = tid; i < NB * CH * HD; i += NTH) {
            int b = i / (CH * HD);
            int r = i % (CH * HD);
            x_sh[b][r >> 6][r & 63] =
                g_h1buf[(size_t)(b0 + b) * TT * HD + (size_t)t0 * HD + r];
        }
        __syncthreads();

        // Chunk-head: prime x-side accumulators for step t0.
#pragma unroll
        for (int b = 0; b < NB; b++) {
            const ulonglong2* xp = (const ulonglong2*)x_sh[b][0];
            u64 x2 = bias2, x3 = 0ULL;
#pragma unroll
            for (int j = 0; j < 16; j++) {
                ulonglong2 xv = xp[j];
                x2 = ffma2(wi[2 * j],     xv.x, x2);
                x3 = ffma2(wi[2 * j + 1], xv.y, x3);
            }
            xa[b][0] = x2; xa[b][1] = x3;
        }

        for (int tt = 0; tt < CH; tt++) {
            const int t = t0 + tt;
            // Deferred output projection for step t-1 on warps 6-7.
            // h_sh holds h(t-1); it is only overwritten in the next phase-2,
            // fenced by barriers these warps also participate in.
            if (t > 0 && tid >= 192) {
                int w = (tid >> 5) - 6, lane = tid & 31;
                float s = wout_sh[lane]      * h_sh[w][lane]
                        + wout_sh[lane + 32] * h_sh[w][lane + 32];
#pragma unroll
                for (int o = 16; o; o >>= 1)
                    s += __shfl_xor_sync(0xffffffffu, s, o);
                if (lane == 0) {
                    float y = s + bo;
                    y = fminf(fmaxf(y, 0.f), 1.f);
                    out[(size_t)(b0 + w) * TT + (t - 1)] = y;
                }
            }
            // --- phase 1: h-side gate accumulation + activation ---
#pragma unroll
            for (int b = 0; b < NB; b++) {
                const ulonglong2* hp = (const ulonglong2*)h_sh[b];
                u64 a0 = 0ULL, a1 = 0ULL;
#pragma unroll
                for (int j = 0; j < 16; j++) {
                    ulonglong2 hv = hp[j];
                    a0 = ffma2(wr[2 * j],     hv.x, a0);
                    a1 = ffma2(wr[2 * j + 1], hv.y, a1);
                }
                float v = pairsum(fadd2(fadd2(a0, a1), fadd2(xa[b][0], xa[b][1])));
                v = (type == 2) ? tanh_fast(v) : sigm(v);
                g_sh[b][g] = v;
            }
            __syncthreads();             // barrier A: gates published
            // --- phase 2 + next-step x-side ---
            if (tid < NB * HD) {
                int b = tid >> 6, j = tid & 63;
                float iv = g_sh[b][j];
                float fv = g_sh[b][64 + j];
                float gv = g_sh[b][128 + j];
                float ov = g_sh[b][192 + j];
                c = fv * c + iv * gv;
                float h = ov * tanh_fast(c);
                h_sh[b][j] = h;
            }
            if (tt + 1 < CH) {
#pragma unroll
                for (int b = 0; b < NB; b++) {
                    const ulonglong2* xp = (const ulonglong2*)x_sh[b][tt + 1];
                    u64 x2 = bias2, x3 = 0ULL;
#pragma unroll
                    for (int j = 0; j < 16; j++) {
                        ulonglong2 xv = xp[j];
                        x2 = ffma2(wi[2 * j],     xv.x, x2);
                        x3 = ffma2(wi[2 * j + 1], xv.y, x3);
                    }
                    xa[b][0] = x2; xa[b][1] = x3;
                }
            }
            __syncthreads();             // barrier B: h(t) published
        }
    }
    // Trailing projection for the final step (h_sh holds h(TT-1)).
    if (tid < 2 * 32) {
        int w = tid >> 5, lane = tid & 31;
        float s = wout_sh[lane]      * h_sh[w][lane]
                + wout_sh[lane + 32] * h_sh[w][lane + 32];
#pragma unroll
        for (int o = 16; o; o >>= 1)
            s += __shfl_xor_sync(0xffffffffu, s, o);
        if (lane == 0) {
            float y = s + bo;
            y = fminf(fmaxf(y, 0.f), 1.f);
            out[(size_t)(b0 + w) * TT + (TT - 1)] = y;
        }
    }
}

extern "C" void kernel_launch(void* const* d_in, const int* in_sizes, int n_in,
                              void* d_out, int out_size)
{
    const float* x     = (const float*)d_in[0];
    const float* Wih0  = (const float*)d_in[1];
    const float* Whh0  = (const float*)d_in[2];
    const float* bih0  = (const float*)d_in[3];
    const float* bhh0  = (const float*)d_in[4];
    const float* Wih1  = (const float*)d_in[5];
    const float* Whh1  = (const float*)d_in[6];
    const float* bih1  = (const float*)d_in[7];
    const float* bhh1  = (const float*)d_in[8];
    const float* Wout  = (const float*)d_in[9];
    const float* bout  = (const float*)d_in[10];
    float* out = (float*)d_out;

    lstm_layer0<<<NCTA, NTH>>>(x, Wih0, Whh0, bih0, bhh0);
    lstm_layer1<<<NCTA, NTH>>>(Wih1, Whh1, bih1, bhh1, Wout, bout, out);
}